// round 9
// baseline (speedup 1.0000x reference)
#include <cuda_runtime.h>
#include <math.h>

#define NN 100000
#define EE 1600000
#define DH 128
#define DOUT 40
#define BN_EPS 1e-5f
#define SB 512
#define NBLK ((NN + SB - 1) / SB)   // 196

// ---------------- scratch (device globals: allocation-free) ----------------
__device__ float g_bufA[(size_t)NN * DH];   // activations (gemm input)
__device__ float g_bufB[(size_t)NN * DH];   // gemm output h
__device__ float g_bufC[(size_t)NN * DH];   // aggregation output
__device__ float g_dinv[NN];
__device__ int   g_cnt[NN];                 // in-degree (int)
__device__ int   g_fill[NN];
__device__ int   g_rowstart[NN];
__device__ int   g_incl[NN];
__device__ int   g_bsum[NBLK];
__device__ int   g_boff[NBLK];
__device__ int   g_esrc[EE];                // CSR: src sorted by dst
__device__ float g_ew[EE];                  // CSR: edge norm
__device__ float g_colsum[DH];
__device__ float g_colsq[DH];
__device__ float g_scale[DH];
__device__ float g_shift[DH];

// ---------------- CSR build ----------------
// NOTE: edge_index is int32 (JAX default x64-disabled downcasts jnp.int64).
__global__ void zero_prep_kernel() {
    int i = blockIdx.x * blockDim.x + threadIdx.x;
    if (i < NN) { g_cnt[i] = 0; g_fill[i] = 0; }
    if (i < DH) { g_colsum[i] = 0.0f; g_colsq[i] = 0.0f; }
}

__global__ void count_kernel(const int* __restrict__ ei) {
    int e = blockIdx.x * blockDim.x + threadIdx.x;
    if (e >= EE) return;
    int d = ei[EE + e];
    if ((unsigned)d < NN) atomicAdd(&g_cnt[d], 1);
}

__global__ void dinv_kernel() {
    int i = blockIdx.x * blockDim.x + threadIdx.x;
    if (i >= NN) return;
    g_dinv[i] = rsqrtf((float)g_cnt[i] + 1.0f);
}

// inclusive scan within 512-blocks
__global__ void scan_block_kernel() {
    __shared__ int sm[SB];
    int i = blockIdx.x * SB + threadIdx.x;
    int v = (i < NN) ? g_cnt[i] : 0;
    sm[threadIdx.x] = v;
    __syncthreads();
#pragma unroll
    for (int off = 1; off < SB; off <<= 1) {
        int t = (threadIdx.x >= off) ? sm[threadIdx.x - off] : 0;
        __syncthreads();
        sm[threadIdx.x] += t;
        __syncthreads();
    }
    if (i < NN) g_incl[i] = sm[threadIdx.x];
    if (threadIdx.x == SB - 1) g_bsum[blockIdx.x] = sm[SB - 1];
}

// scan of block sums (NBLK <= 256), one block of 256 threads
__global__ void scan_bsum_kernel() {
    __shared__ int sm[256];
    int v = (threadIdx.x < NBLK) ? g_bsum[threadIdx.x] : 0;
    sm[threadIdx.x] = v;
    __syncthreads();
#pragma unroll
    for (int off = 1; off < 256; off <<= 1) {
        int t = (threadIdx.x >= off) ? sm[threadIdx.x - off] : 0;
        __syncthreads();
        sm[threadIdx.x] += t;
        __syncthreads();
    }
    if (threadIdx.x < NBLK) g_boff[threadIdx.x] = sm[threadIdx.x] - v;  // exclusive
}

__global__ void scan_finalize_kernel() {
    int i = blockIdx.x * blockDim.x + threadIdx.x;
    if (i >= NN) return;
    g_rowstart[i] = g_incl[i] + g_boff[i / SB] - g_cnt[i];
}

__global__ void fill_kernel(const int* __restrict__ ei) {
    int e = blockIdx.x * blockDim.x + threadIdx.x;
    if (e >= EE) return;
    int s = ei[e];
    int d = ei[EE + e];
    if ((unsigned)s >= NN || (unsigned)d >= NN) return;
    int pos = g_rowstart[d] + atomicAdd(&g_fill[d], 1);
    g_esrc[pos] = s;
    g_ew[pos] = g_dinv[s] * g_dinv[d];
}

// ---------------- fp32 GEMM: C[M,N] = A[M,K] @ B[K,N] ----------------
__global__ void sgemm_kernel(const float* __restrict__ A, const float* __restrict__ B,
                             float* __restrict__ C, int M, int N, int K) {
    const int BM = 64, BN = 64, BK = 16, TM = 4, TN = 4;
    __shared__ float As[BK][BM];
    __shared__ float Bs[BK][BN];

    int tid  = threadIdx.x;
    int trow = tid / 16;
    int tcol = tid % 16;
    int rowBase = blockIdx.y * BM;
    int colBase = blockIdx.x * BN;

    int aR = tid >> 2;
    int aC = (tid & 3) * 4;
    int bR = tid >> 4;
    int bC = (tid & 15) * 4;

    float acc[TM][TN];
#pragma unroll
    for (int i = 0; i < TM; i++)
#pragma unroll
        for (int j = 0; j < TN; j++) acc[i][j] = 0.0f;

    for (int k0 = 0; k0 < K; k0 += BK) {
        float4 av = make_float4(0.f, 0.f, 0.f, 0.f);
        int gr = rowBase + aR;
        if (gr < M) av = *(const float4*)&A[(size_t)gr * K + k0 + aC];
        As[aC + 0][aR] = av.x;
        As[aC + 1][aR] = av.y;
        As[aC + 2][aR] = av.z;
        As[aC + 3][aR] = av.w;

        float4 bv = make_float4(0.f, 0.f, 0.f, 0.f);
        int gc = colBase + bC;
        const float* Brow = &B[(size_t)(k0 + bR) * N];
        if (gc + 3 < N) {
            bv = *(const float4*)&Brow[gc];
        } else {
            if (gc + 0 < N) bv.x = Brow[gc + 0];
            if (gc + 1 < N) bv.y = Brow[gc + 1];
            if (gc + 2 < N) bv.z = Brow[gc + 2];
        }
        Bs[bR][bC + 0] = bv.x;
        Bs[bR][bC + 1] = bv.y;
        Bs[bR][bC + 2] = bv.z;
        Bs[bR][bC + 3] = bv.w;

        __syncthreads();

#pragma unroll
        for (int k = 0; k < BK; k++) {
            float am[TM], bn[TN];
#pragma unroll
            for (int i = 0; i < TM; i++) am[i] = As[k][trow * TM + i];
#pragma unroll
            for (int j = 0; j < TN; j++) bn[j] = Bs[k][tcol * TN + j];
#pragma unroll
            for (int i = 0; i < TM; i++)
#pragma unroll
                for (int j = 0; j < TN; j++) acc[i][j] += am[i] * bn[j];
        }
        __syncthreads();
    }

#pragma unroll
    for (int i = 0; i < TM; i++) {
        int gr = rowBase + trow * TM + i;
        if (gr >= M) continue;
#pragma unroll
        for (int j = 0; j < TN; j++) {
            int gc = colBase + tcol * TN + j;
            if (gc < N) C[(size_t)gr * N + gc] = acc[i][j];
        }
    }
}

// ---------------- CSR gather aggregation (no atomics) ----------------
// One warp per dst node; lane q accumulates float4 features [4q, 4q+4).
__global__ void aggregate128_kernel(const float* __restrict__ H, float* __restrict__ C) {
    int warp = (blockIdx.x * blockDim.x + threadIdx.x) >> 5;
    int lane = threadIdx.x & 31;
    if (warp >= NN) return;
    int start = g_rowstart[warp];
    int end   = start + g_cnt[warp];
    const float4* H4 = (const float4*)H;
    float4 acc = make_float4(0.f, 0.f, 0.f, 0.f);
    int j = start;
    for (; j + 1 < end; j += 2) {
        int   s0 = g_esrc[j],     s1 = g_esrc[j + 1];
        float w0 = g_ew[j],       w1 = g_ew[j + 1];
        float4 h0 = H4[(size_t)s0 * 32 + lane];
        float4 h1 = H4[(size_t)s1 * 32 + lane];
        acc.x += h0.x * w0; acc.y += h0.y * w0; acc.z += h0.z * w0; acc.w += h0.w * w0;
        acc.x += h1.x * w1; acc.y += h1.y * w1; acc.z += h1.z * w1; acc.w += h1.w * w1;
    }
    if (j < end) {
        int s = g_esrc[j]; float w = g_ew[j];
        float4 h = H4[(size_t)s * 32 + lane];
        acc.x += h.x * w; acc.y += h.y * w; acc.z += h.z * w; acc.w += h.w * w;
    }
    ((float4*)C)[(size_t)warp * 32 + lane] = acc;
}

// D=40: one warp per node, lanes 0..9 hold one float4 each.
__global__ void aggregate40_kernel(const float* __restrict__ H, float* __restrict__ C) {
    int warp = (blockIdx.x * blockDim.x + threadIdx.x) >> 5;
    int lane = threadIdx.x & 31;
    if (warp >= NN) return;
    int start = g_rowstart[warp];
    int end   = start + g_cnt[warp];
    const float4* H4 = (const float4*)H;
    float4 acc = make_float4(0.f, 0.f, 0.f, 0.f);
    for (int j = start; j < end; j++) {
        int s = g_esrc[j]; float w = g_ew[j];
        if (lane < 10) {
            float4 h = H4[(size_t)s * 10 + lane];
            acc.x += h.x * w; acc.y += h.y * w; acc.z += h.z * w; acc.w += h.w * w;
        }
    }
    if (lane < 10) ((float4*)C)[(size_t)warp * 10 + lane] = acc;
}

// ---------------- finalize + BN column stats (D=128) ----------------
__global__ void finalize_stats_kernel(float* __restrict__ C, const float* __restrict__ H,
                                      const float* __restrict__ bias) {
    int f  = threadIdx.x;            // 0..127
    int r0 = blockIdx.x * 64;
    int r1 = r0 + 64;
    if (r1 > NN) r1 = NN;
    float b = bias[f];
    float s = 0.0f, s2 = 0.0f;
    for (int r = r0; r < r1; r++) {
        float di = g_dinv[r];
        size_t o = (size_t)r * DH + f;
        float v = C[o] + H[o] * (di * di) + b;
        C[o] = v;
        s += v;
        s2 += v * v;
    }
    atomicAdd(&g_colsum[f], s);
    atomicAdd(&g_colsq[f], s2);
}

__global__ void bn_prep_kernel(const float* __restrict__ g, const float* __restrict__ be) {
    int f = threadIdx.x;
    if (f >= DH) return;
    float mu  = g_colsum[f] / (float)NN;
    float var = g_colsq[f] / (float)NN - mu * mu;
    float sc  = g[f] * rsqrtf(var + BN_EPS);
    g_scale[f] = sc;
    g_shift[f] = be[f] - mu * sc;
}

__global__ void bn_relu_kernel(const float* __restrict__ C, float* __restrict__ A) {
    size_t idx = (size_t)blockIdx.x * blockDim.x + threadIdx.x;
    if (idx >= (size_t)NN * DH) return;
    int f = (int)(idx & (DH - 1));
    float v = C[idx] * g_scale[f] + g_shift[f];
    A[idx] = v > 0.0f ? v : 0.0f;
}

__global__ void zero_stats_kernel() {
    int i = threadIdx.x;
    if (i < DH) { g_colsum[i] = 0.0f; g_colsq[i] = 0.0f; }
}

// ---------------- final layer finalize (D=40, no BN) ----------------
__global__ void finalize40_kernel(const float* __restrict__ C, const float* __restrict__ H,
                                  const float* __restrict__ bf, float* __restrict__ out) {
    size_t idx = (size_t)blockIdx.x * blockDim.x + threadIdx.x;
    if (idx >= (size_t)NN * DOUT) return;
    int r = (int)(idx / DOUT);
    int f = (int)(idx % DOUT);
    float di = g_dinv[r];
    out[idx] = C[idx] + H[idx] * (di * di) + bf[f];
}

// ---------------- row log-softmax (D=40), warp per row ----------------
__global__ void logsoftmax_kernel(float* __restrict__ out) {
    int warp = (blockIdx.x * blockDim.x + threadIdx.x) >> 5;
    int lane = threadIdx.x & 31;
    if (warp >= NN) return;
    size_t base = (size_t)warp * DOUT;

    float v0 = (lane < DOUT) ? out[base + lane] : -1e30f;
    float v1 = (lane + 32 < DOUT) ? out[base + lane + 32] : -1e30f;

    float m = fmaxf(v0, v1);
#pragma unroll
    for (int o = 16; o > 0; o >>= 1) m = fmaxf(m, __shfl_xor_sync(0xffffffffu, m, o));

    float s = 0.0f;
    if (lane < DOUT) s += expf(v0 - m);
    if (lane + 32 < DOUT) s += expf(v1 - m);
#pragma unroll
    for (int o = 16; o > 0; o >>= 1) s += __shfl_xor_sync(0xffffffffu, s, o);

    float ls = m + logf(s);
    if (lane < DOUT) out[base + lane] = v0 - ls;
    if (lane + 32 < DOUT) out[base + lane + 32] = v1 - ls;
}

// ---------------- host launch ----------------
extern "C" void kernel_launch(void* const* d_in, const int* in_sizes, int n_in,
                              void* d_out, int out_size) {
    const float* x   = (const float*)d_in[0];
    const int*   ei  = (const int*)d_in[1];    // int32 edge_index (JAX x64 disabled)
    const float* W1  = (const float*)d_in[2];
    const float* b1  = (const float*)d_in[3];
    const float* g1  = (const float*)d_in[4];
    const float* be1 = (const float*)d_in[5];
    const float* W2  = (const float*)d_in[6];
    const float* b2  = (const float*)d_in[7];
    const float* g2  = (const float*)d_in[8];
    const float* be2 = (const float*)d_in[9];
    const float* Wf  = (const float*)d_in[10];
    const float* bf  = (const float*)d_in[11];
    float* out = (float*)d_out;

    float *bufA, *bufB, *bufC;
    cudaGetSymbolAddress((void**)&bufA, g_bufA);
    cudaGetSymbolAddress((void**)&bufB, g_bufB);
    cudaGetSymbolAddress((void**)&bufC, g_bufC);

    const int T = 256;
    const size_t nElem = (size_t)NN * DH;
    const int nBlocksElem = (int)((nElem + T - 1) / T);
    const int nBlocksN = (NN + T - 1) / T;
    const int nBlocksE = (EE + T - 1) / T;

    // --- CSR build (per launch; deterministic work) ---
    zero_prep_kernel<<<nBlocksN, T>>>();
    count_kernel<<<nBlocksE, T>>>(ei);
    dinv_kernel<<<nBlocksN, T>>>();
    scan_block_kernel<<<NBLK, SB>>>();
    scan_bsum_kernel<<<1, 256>>>();
    scan_finalize_kernel<<<nBlocksN, T>>>();
    fill_kernel<<<nBlocksE, T>>>(ei);

    dim3 gemmGrid128(2, (NN + 63) / 64);
    dim3 gemmGrid40(1, (NN + 63) / 64);
    const int aggBlocks = (NN * 32 + T - 1) / T;   // one warp per node

    // ---------------- layer 1 ----------------
    sgemm_kernel<<<gemmGrid128, T>>>(x, W1, bufB, NN, DH, DH);
    aggregate128_kernel<<<aggBlocks, T>>>(bufB, bufC);
    finalize_stats_kernel<<<(NN + 63) / 64, 128>>>(bufC, bufB, b1);
    bn_prep_kernel<<<1, 128>>>(g1, be1);
    bn_relu_kernel<<<nBlocksElem, T>>>(bufC, bufA);
    zero_stats_kernel<<<1, 128>>>();

    // ---------------- layer 2 ----------------
    sgemm_kernel<<<gemmGrid128, T>>>(bufA, W2, bufB, NN, DH, DH);
    aggregate128_kernel<<<aggBlocks, T>>>(bufB, bufC);
    finalize_stats_kernel<<<(NN + 63) / 64, 128>>>(bufC, bufB, b2);
    bn_prep_kernel<<<1, 128>>>(g2, be2);
    bn_relu_kernel<<<nBlocksElem, T>>>(bufC, bufA);

    // ---------------- layer 3 (output, D=40) ----------------
    sgemm_kernel<<<gemmGrid40, T>>>(bufA, Wf, bufB, NN, DOUT, DH);
    aggregate40_kernel<<<aggBlocks, T>>>(bufB, bufC);
    finalize40_kernel<<<(int)(((size_t)NN * DOUT + T - 1) / T), T>>>(bufC, bufB, bf, out);

    // ---------------- log-softmax ----------------
    logsoftmax_kernel<<<aggBlocks, T>>>(out);
}